// round 11
// baseline (speedup 1.0000x reference)
#include <cuda_runtime.h>
#include <cstddef>

// GaussianIntegral2D — R10 structure with hidden-instruction strip:
//  * exp2 via inline PTX ex2.approx.ftz.f32 (single MUFU regardless of
//    compile flags; exp2f is a ~10-instr software path without fast-math).
//  * ping-pong unrolled x2 grid-stride loop (no P=Pn register rotation).
//  * per-thread store base pointer, inner store offsets are immediates.
// Kept: 8-lanes-per-pair, register quadrature table, 1-ahead param
// prefetch, aligned STG.128, quadratic-poly exponent, TPB=128.

#define NEG_HALF_LOG2E_F (-0.7213475204444817f) // -0.5 * log2(e)
#define INV_2PI_F 0.15915494309189535f          // 1/(2*pi)

static constexpr int Q     = 49;
static constexpr int TPB   = 128;
static constexpr int ROW_B = 8 * Q;             // 392 bytes per pair row

struct Params { float2 m, t; float4 c, r; };

__device__ __forceinline__ float ex2f(float x) {
    float y;
    asm("ex2.approx.ftz.f32 %0, %1;" : "=f"(y) : "f"(x));
    return y;
}

__device__ __forceinline__ void load_params(
    const float* __restrict__ means, const float* __restrict__ covars,
    const float* __restrict__ rots,  const float* __restrict__ trans,
    int p, Params& P)
{
    P.m = reinterpret_cast<const float2*>(means)[p];
    P.c = reinterpret_cast<const float4*>(covars)[p];   // c00 c01 c10 c11
    P.r = reinterpret_cast<const float4*>(rots)[p];
    P.t = reinterpret_cast<const float2*>(trans)[p];
}

struct QuadReg {
    float ex[6], ey[6], w[6];
    float ext, eyt, wt;
};

__device__ __forceinline__ void pair_body(
    const Params& P, const QuadReg& qr,
    int s, int g, int phi, char* outb, float* oint, bool inb)
{
    if (!inb) return;

    // Per-pair quadratic coefficients (amortized over 49 points).
    const float det   = P.c.x * P.c.w - P.c.y * P.c.z;
    const float k2    = NEG_HALF_LOG2E_F * __frcp_rn(det);
    const float scale = INV_2PI_F * __frsqrt_rn(det);
    const float Qa = k2 * P.c.w;
    const float Qb = -k2 * (P.c.y + P.c.z);
    const float Qc = k2 * P.c.x;
    const float D  = -fmaf(2.0f * Qa, P.m.x, Qb * P.m.y);
    const float E  = -fmaf(2.0f * Qc, P.m.y, Qb * P.m.x);
    const float F  = fmaf(P.m.x, fmaf(Qa, P.m.x, Qb * P.m.y),
                          Qc * P.m.y * P.m.y);

    float4* const st = reinterpret_cast<float4*>(outb + 8 * phi + 16 * s);

    float acc0 = 0.0f, acc1 = 0.0f;

    #pragma unroll
    for (int k = 0; k < 3; ++k) {
        const float px0 = fmaf(P.r.x, qr.ex[2*k],   fmaf(P.r.y, qr.ey[2*k],   P.t.x));
        const float py0 = fmaf(P.r.z, qr.ex[2*k],   fmaf(P.r.w, qr.ey[2*k],   P.t.y));
        const float px1 = fmaf(P.r.x, qr.ex[2*k+1], fmaf(P.r.y, qr.ey[2*k+1], P.t.x));
        const float py1 = fmaf(P.r.z, qr.ex[2*k+1], fmaf(P.r.w, qr.ey[2*k+1], P.t.y));

        __stcs(st + 8 * k, make_float4(px0, py0, px1, py1)); // STG.128, imm offset

        float t1 = fmaf(Qa, px0, fmaf(Qb, py0, D));
        float t2 = fmaf(Qc, py0, E);
        acc0 = fmaf(qr.w[2*k], ex2f(fmaf(px0, t1, fmaf(py0, t2, F))), acc0);

        t1 = fmaf(Qa, px1, fmaf(Qb, py1, D));
        t2 = fmaf(Qc, py1, E);
        acc1 = fmaf(qr.w[2*k+1], ex2f(fmaf(px1, t1, fmaf(py1, t2, F))), acc1);
    }

    // Scalar tail point (one per pair): q=0 (phi=1) or q=48 (phi=0).
    if (s == 0) {
        const float px = fmaf(P.r.x, qr.ext, fmaf(P.r.y, qr.eyt, P.t.x));
        const float py = fmaf(P.r.z, qr.ext, fmaf(P.r.w, qr.eyt, P.t.y));
        __stcs(reinterpret_cast<float2*>(outb + (phi ? 0 : 8 * (Q - 1))),
               make_float2(px, py));
        const float t1 = fmaf(Qa, px, fmaf(Qb, py, D));
        const float t2 = fmaf(Qc, py, E);
        acc0 = fmaf(qr.wt, ex2f(fmaf(px, t1, fmaf(py, t2, F))), acc0);
    }

    // Reduce over the 8 lanes of this group.
    float acc = acc0 + acc1;
    const unsigned gmask = 0xFFu << (g * 8);
    acc += __shfl_down_sync(gmask, acc, 4, 8);
    acc += __shfl_down_sync(gmask, acc, 2, 8);
    acc += __shfl_down_sync(gmask, acc, 1, 8);

    if (s == 0)
        *oint = fminf(fmaxf(scale * acc, 0.0f), 1.0f);
}

__global__ void __launch_bounds__(TPB)
gauss_integral_kernel(const float* __restrict__ means,   // [P,2]
                      const float* __restrict__ covars,  // [P,4]
                      const float* __restrict__ rots,    // [P,4]
                      const float* __restrict__ trans,   // [P,2]
                      const float* __restrict__ eta,     // [2,Q]
                      const float* __restrict__ wts,     // [Q]
                      float* __restrict__ out_pts,       // [P,Q,2]
                      float* __restrict__ out_int,       // [P]
                      int npair)
{
    const int tid  = threadIdx.x;
    const int lane = tid & 31;
    const int s    = lane & 7;
    const int g    = lane >> 3;
    const int phi  = g & 1;

    // Register-resident quadrature data: 6 points per thread (2 per slot).
    QuadReg qr;
    #pragma unroll
    for (int k = 0; k < 3; ++k) {
        const int u = 2 * (s + 8 * k) + phi;
        qr.ex[2*k]   = __ldg(eta + u);     qr.ey[2*k]   = __ldg(eta + Q + u);
        qr.ex[2*k+1] = __ldg(eta + u + 1); qr.ey[2*k+1] = __ldg(eta + Q + u + 1);
        qr.w[2*k]    = __ldg(wts + u);
        qr.w[2*k+1]  = __ldg(wts + u + 1);
    }
    const int qt = phi ? 0 : Q - 1;
    qr.ext = __ldg(eta + qt); qr.eyt = __ldg(eta + Q + qt);
    qr.wt  = __ldg(wts + qt);

    const int warp_g = (blockIdx.x * TPB + tid) >> 5;
    const int nwarp  = (gridDim.x * TPB) >> 5;
    const int nquad  = (npair + 3) >> 2;

    int qid = warp_g;
    if (qid >= nquad) return;
    int p = qid * 4 + g;

    const size_t step_b = (size_t)(4 * nwarp) * (size_t)ROW_B;
    const int    pstep  = 4 * nwarp;
    char*  outb = reinterpret_cast<char*>(out_pts) + (size_t)p * (size_t)ROW_B;
    float* oint = out_int + p;

    Params Pa, Pb;
    if (p < npair)
        load_params(means, covars, rots, trans, p, Pa);

    // Ping-pong unrolled x2: no register rotation between iterations.
    for (;;) {
        // --- iteration A: consume Pa, prefetch Pb ---
        bool vn = (qid + nwarp) < nquad;
        if (vn && (p + pstep) < npair)
            load_params(means, covars, rots, trans, p + pstep, Pb);
        pair_body(Pa, qr, s, g, phi, outb, oint, p < npair);
        if (!vn) break;
        qid += nwarp; p += pstep; outb += step_b; oint += pstep;

        // --- iteration B: consume Pb, prefetch Pa ---
        vn = (qid + nwarp) < nquad;
        if (vn && (p + pstep) < npair)
            load_params(means, covars, rots, trans, p + pstep, Pa);
        pair_body(Pb, qr, s, g, phi, outb, oint, p < npair);
        if (!vn) break;
        qid += nwarp; p += pstep; outb += step_b; oint += pstep;
    }
}

extern "C" void kernel_launch(void* const* d_in, const int* in_sizes, int n_in,
                              void* d_out, int out_size)
{
    const float* means  = (const float*)d_in[0];
    const float* covars = (const float*)d_in[1];
    const float* rots   = (const float*)d_in[2];
    const float* trans  = (const float*)d_in[3];
    const float* eta    = (const float*)d_in[4];
    const float* wts    = (const float*)d_in[5];

    const int npair = in_sizes[0] / 2;

    float* out_pts = (float*)d_out;
    float* out_int = out_pts + (size_t)npair * (size_t)(2 * Q);

    const int blocks = 4096;     // 16384 warps, ~8 quads each at P=524288
    gauss_integral_kernel<<<blocks, TPB>>>(
        means, covars, rots, trans, eta, wts, out_pts, out_int, npair);
}

// round 12
// speedup vs baseline: 1.0240x; 1.0240x over previous
#include <cuda_runtime.h>
#include <cstddef>

// GaussianIntegral2D — R10 loop structure (grid-stride, 1-ahead prefetch
// with simple register rotation) + R11's ex2.approx PTX strip, with
// registers capped at 64 (__launch_bounds__(128,8)) to restore occupancy.
// R11 lesson: post-strip the kernel is LATENCY-bound — warps, not fewer
// instructions, are what buy DRAM throughput now.

#define NEG_HALF_LOG2E_F (-0.7213475204444817f) // -0.5 * log2(e)
#define INV_2PI_F 0.15915494309189535f          // 1/(2*pi)

static constexpr int Q     = 49;
static constexpr int TPB   = 128;
static constexpr int ROW_B = 8 * Q;             // 392 bytes per pair row

struct Params { float2 m, t; float4 c, r; };

__device__ __forceinline__ float ex2f(float x) {
    float y;
    asm("ex2.approx.ftz.f32 %0, %1;" : "=f"(y) : "f"(x));
    return y;
}

__device__ __forceinline__ void load_params(
    const float* __restrict__ means, const float* __restrict__ covars,
    const float* __restrict__ rots,  const float* __restrict__ trans,
    int p, Params& P)
{
    P.m = reinterpret_cast<const float2*>(means)[p];
    P.c = reinterpret_cast<const float4*>(covars)[p];   // c00 c01 c10 c11
    P.r = reinterpret_cast<const float4*>(rots)[p];
    P.t = reinterpret_cast<const float2*>(trans)[p];
}

__global__ void __launch_bounds__(TPB, 8)
gauss_integral_kernel(const float* __restrict__ means,   // [P,2]
                      const float* __restrict__ covars,  // [P,4]
                      const float* __restrict__ rots,    // [P,4]
                      const float* __restrict__ trans,   // [P,2]
                      const float* __restrict__ eta,     // [2,Q]
                      const float* __restrict__ wts,     // [Q]
                      float* __restrict__ out_pts,       // [P,Q,2]
                      float* __restrict__ out_int,       // [P]
                      int npair)
{
    const int tid  = threadIdx.x;
    const int lane = tid & 31;
    const int s    = lane & 7;       // slot phase within group
    const int g    = lane >> 3;      // group within warp
    const int phi  = g & 1;          // pair parity — fixed per thread

    // Register-resident quadrature data: 6 points per thread (2 per slot).
    float ex[6], ey[6], w[6];
    #pragma unroll
    for (int k = 0; k < 3; ++k) {
        const int u = 2 * (s + 8 * k) + phi;     // 0..47 (phi=0) / 1..48 (phi=1)
        ex[2*k]   = __ldg(eta + u);     ey[2*k]   = __ldg(eta + Q + u);
        ex[2*k+1] = __ldg(eta + u + 1); ey[2*k+1] = __ldg(eta + Q + u + 1);
        w[2*k]    = __ldg(wts + u);
        w[2*k+1]  = __ldg(wts + u + 1);
    }
    // Tail point (s==0 lane only): q=0 for phi=1, q=48 for phi=0.
    const int qt = phi ? 0 : Q - 1;
    const float ext = __ldg(eta + qt), eyt = __ldg(eta + Q + qt);
    const float wt  = __ldg(wts + qt);

    const int warp_g = (blockIdx.x * TPB + tid) >> 5;
    const int nwarp  = (gridDim.x * TPB) >> 5;
    const int nquad  = (npair + 3) >> 2;

    int  qid   = warp_g;
    bool valid = (qid < nquad);
    int  p     = qid * 4 + g;

    // Loop-invariant pointer strides (hoisted address math).
    const size_t step_b = (size_t)(4 * nwarp) * (size_t)ROW_B;
    char*        outb   = reinterpret_cast<char*>(out_pts)
                        + (size_t)p * (size_t)ROW_B;
    float*       oint   = out_int + p;
    const int    pstep  = 4 * nwarp;

    Params P;
    if (valid && p < npair)
        load_params(means, covars, rots, trans, p, P);

    while (valid) {
        // ---- prefetch next iteration's params ----
        const int  qn    = qid + nwarp;
        const bool vnext = (qn < nquad);
        const int  pn    = p + pstep;
        Params Pn;
        if (vnext && pn < npair)
            load_params(means, covars, rots, trans, pn, Pn);

        // ---- compute current pair ----
        if (p < npair) {
            // Per-pair quadratic coefficients (amortized over 49 points).
            const float det   = P.c.x * P.c.w - P.c.y * P.c.z;
            const float k2    = NEG_HALF_LOG2E_F * __frcp_rn(det);
            const float scale = INV_2PI_F * __frsqrt_rn(det);
            const float Qa = k2 * P.c.w;
            const float Qb = -k2 * (P.c.y + P.c.z);
            const float Qc = k2 * P.c.x;
            const float D  = -fmaf(2.0f * Qa, P.m.x, Qb * P.m.y);
            const float E  = -fmaf(2.0f * Qc, P.m.y, Qb * P.m.x);
            const float F  = fmaf(P.m.x, fmaf(Qa, P.m.x, Qb * P.m.y),
                                  Qc * P.m.y * P.m.y);

            float4* const st = reinterpret_cast<float4*>(outb + 8 * phi + 16 * s);

            float acc0 = 0.0f, acc1 = 0.0f;

            #pragma unroll
            for (int k = 0; k < 3; ++k) {
                const float px0 = fmaf(P.r.x, ex[2*k],   fmaf(P.r.y, ey[2*k],   P.t.x));
                const float py0 = fmaf(P.r.z, ex[2*k],   fmaf(P.r.w, ey[2*k],   P.t.y));
                const float px1 = fmaf(P.r.x, ex[2*k+1], fmaf(P.r.y, ey[2*k+1], P.t.x));
                const float py1 = fmaf(P.r.z, ex[2*k+1], fmaf(P.r.w, ey[2*k+1], P.t.y));

                __stcs(st + 8 * k, make_float4(px0, py0, px1, py1)); // STG.128

                float t1 = fmaf(Qa, px0, fmaf(Qb, py0, D));
                float t2 = fmaf(Qc, py0, E);
                acc0 = fmaf(w[2*k], ex2f(fmaf(px0, t1, fmaf(py0, t2, F))), acc0);

                t1 = fmaf(Qa, px1, fmaf(Qb, py1, D));
                t2 = fmaf(Qc, py1, E);
                acc1 = fmaf(w[2*k+1], ex2f(fmaf(px1, t1, fmaf(py1, t2, F))), acc1);
            }

            // Scalar tail point (one per pair).
            if (s == 0) {
                const float px = fmaf(P.r.x, ext, fmaf(P.r.y, eyt, P.t.x));
                const float py = fmaf(P.r.z, ext, fmaf(P.r.w, eyt, P.t.y));
                __stcs(reinterpret_cast<float2*>(outb + (phi ? 0 : 8 * (Q - 1))),
                       make_float2(px, py));
                const float t1 = fmaf(Qa, px, fmaf(Qb, py, D));
                const float t2 = fmaf(Qc, py, E);
                acc0 = fmaf(wt, ex2f(fmaf(px, t1, fmaf(py, t2, F))), acc0);
            }

            // Reduce over the 8 lanes of this group.
            float acc = acc0 + acc1;
            const unsigned gmask = 0xFFu << (g * 8);
            acc += __shfl_down_sync(gmask, acc, 4, 8);
            acc += __shfl_down_sync(gmask, acc, 2, 8);
            acc += __shfl_down_sync(gmask, acc, 1, 8);

            if (s == 0)
                *oint = fminf(fmaxf(scale * acc, 0.0f), 1.0f);
        }

        P = Pn; qid = qn; p = pn; valid = vnext;
        outb += step_b; oint += pstep;
    }
}

extern "C" void kernel_launch(void* const* d_in, const int* in_sizes, int n_in,
                              void* d_out, int out_size)
{
    const float* means  = (const float*)d_in[0];
    const float* covars = (const float*)d_in[1];
    const float* rots   = (const float*)d_in[2];
    const float* trans  = (const float*)d_in[3];
    const float* eta    = (const float*)d_in[4];
    const float* wts    = (const float*)d_in[5];

    const int npair = in_sizes[0] / 2;

    float* out_pts = (float*)d_out;
    float* out_int = out_pts + (size_t)npair * (size_t)(2 * Q);

    const int blocks = 4096;     // 16384 warps, ~8 quads each at P=524288
    gauss_integral_kernel<<<blocks, TPB>>>(
        means, covars, rots, trans, eta, wts, out_pts, out_int, npair);
}

// round 13
// speedup vs baseline: 1.1096x; 1.0836x over previous
#include <cuda_runtime.h>
#include <cstddef>

// GaussianIntegral2D — R10 loop (grid-stride + 1-ahead prefetch, uncapped
// regs) + ex2.approx strip + PHASE-REORDERED pair body:
//   phase 1: all 6 rotated points (only needs r,t)
//   phase 2: all 3 STG.128 back-to-back  -> 3x store burst, issued ~40
//            instructions earlier, zero extra registers
//   phase 3: coefficient chain (rcp/rsqrt) + exp accumulation while the
//            stores drain.
// R12 lesson: never cap regs (ptxas remat doubles ALU). R11 lesson: no
// ping-pong double buffer (reg cost kills occupancy).

#define NEG_HALF_LOG2E_F (-0.7213475204444817f) // -0.5 * log2(e)
#define INV_2PI_F 0.15915494309189535f          // 1/(2*pi)

static constexpr int Q     = 49;
static constexpr int TPB   = 128;
static constexpr int ROW_B = 8 * Q;             // 392 bytes per pair row

struct Params { float2 m, t; float4 c, r; };

__device__ __forceinline__ float ex2f(float x) {
    float y;
    asm("ex2.approx.ftz.f32 %0, %1;" : "=f"(y) : "f"(x));
    return y;
}

__device__ __forceinline__ void load_params(
    const float* __restrict__ means, const float* __restrict__ covars,
    const float* __restrict__ rots,  const float* __restrict__ trans,
    int p, Params& P)
{
    P.m = reinterpret_cast<const float2*>(means)[p];
    P.c = reinterpret_cast<const float4*>(covars)[p];   // c00 c01 c10 c11
    P.r = reinterpret_cast<const float4*>(rots)[p];
    P.t = reinterpret_cast<const float2*>(trans)[p];
}

__global__ void __launch_bounds__(TPB)
gauss_integral_kernel(const float* __restrict__ means,   // [P,2]
                      const float* __restrict__ covars,  // [P,4]
                      const float* __restrict__ rots,    // [P,4]
                      const float* __restrict__ trans,   // [P,2]
                      const float* __restrict__ eta,     // [2,Q]
                      const float* __restrict__ wts,     // [Q]
                      float* __restrict__ out_pts,       // [P,Q,2]
                      float* __restrict__ out_int,       // [P]
                      int npair)
{
    const int tid  = threadIdx.x;
    const int lane = tid & 31;
    const int s    = lane & 7;       // slot phase within group
    const int g    = lane >> 3;      // group within warp
    const int phi  = g & 1;          // pair parity — fixed per thread

    // Register-resident quadrature data: 6 points per thread (2 per slot).
    float ex[6], ey[6], w[6];
    #pragma unroll
    for (int k = 0; k < 3; ++k) {
        const int u = 2 * (s + 8 * k) + phi;     // 0..47 (phi=0) / 1..48 (phi=1)
        ex[2*k]   = __ldg(eta + u);     ey[2*k]   = __ldg(eta + Q + u);
        ex[2*k+1] = __ldg(eta + u + 1); ey[2*k+1] = __ldg(eta + Q + u + 1);
        w[2*k]    = __ldg(wts + u);
        w[2*k+1]  = __ldg(wts + u + 1);
    }
    // Tail point (s==0 lane only): q=0 for phi=1, q=48 for phi=0.
    const int qt = phi ? 0 : Q - 1;
    const float ext = __ldg(eta + qt), eyt = __ldg(eta + Q + qt);
    const float wt  = __ldg(wts + qt);

    const int warp_g = (blockIdx.x * TPB + tid) >> 5;
    const int nwarp  = (gridDim.x * TPB) >> 5;
    const int nquad  = (npair + 3) >> 2;

    int  qid   = warp_g;
    bool valid = (qid < nquad);
    int  p     = qid * 4 + g;

    const size_t step_b = (size_t)(4 * nwarp) * (size_t)ROW_B;
    char*        outb   = reinterpret_cast<char*>(out_pts)
                        + (size_t)p * (size_t)ROW_B;
    float*       oint   = out_int + p;
    const int    pstep  = 4 * nwarp;

    Params P;
    if (valid && p < npair)
        load_params(means, covars, rots, trans, p, P);

    while (valid) {
        // ---- prefetch next iteration's params ----
        const int  qn    = qid + nwarp;
        const bool vnext = (qn < nquad);
        const int  pn    = p + pstep;
        Params Pn;
        if (vnext && pn < npair)
            load_params(means, covars, rots, trans, pn, Pn);

        if (p < npair) {
            // ---- phase 1: all rotated points (needs only r, t) ----
            float px[6], py[6];
            #pragma unroll
            for (int k = 0; k < 6; ++k) {
                px[k] = fmaf(P.r.x, ex[k], fmaf(P.r.y, ey[k], P.t.x));
                py[k] = fmaf(P.r.z, ex[k], fmaf(P.r.w, ey[k], P.t.y));
            }
            float pxt = 0.f, pyt = 0.f;
            if (s == 0) {
                pxt = fmaf(P.r.x, ext, fmaf(P.r.y, eyt, P.t.x));
                pyt = fmaf(P.r.z, ext, fmaf(P.r.w, eyt, P.t.y));
            }

            // ---- phase 2: store burst (3x STG.128 back-to-back) ----
            float4* const st = reinterpret_cast<float4*>(outb + 8 * phi + 16 * s);
            __stcs(st,      make_float4(px[0], py[0], px[1], py[1]));
            __stcs(st + 8,  make_float4(px[2], py[2], px[3], py[3]));
            __stcs(st + 16, make_float4(px[4], py[4], px[5], py[5]));
            if (s == 0)
                __stcs(reinterpret_cast<float2*>(outb + (phi ? 0 : 8 * (Q - 1))),
                       make_float2(pxt, pyt));

            // ---- phase 3: coefficients + exp accumulation (stores drain) ----
            const float det   = P.c.x * P.c.w - P.c.y * P.c.z;
            const float k2    = NEG_HALF_LOG2E_F * __frcp_rn(det);
            const float scale = INV_2PI_F * __frsqrt_rn(det);
            const float Qa = k2 * P.c.w;
            const float Qb = -k2 * (P.c.y + P.c.z);
            const float Qc = k2 * P.c.x;
            const float D  = -fmaf(2.0f * Qa, P.m.x, Qb * P.m.y);
            const float E  = -fmaf(2.0f * Qc, P.m.y, Qb * P.m.x);
            const float F  = fmaf(P.m.x, fmaf(Qa, P.m.x, Qb * P.m.y),
                                  Qc * P.m.y * P.m.y);

            float acc0 = 0.0f, acc1 = 0.0f;
            #pragma unroll
            for (int k = 0; k < 3; ++k) {
                float t1 = fmaf(Qa, px[2*k], fmaf(Qb, py[2*k], D));
                float t2 = fmaf(Qc, py[2*k], E);
                acc0 = fmaf(w[2*k],
                            ex2f(fmaf(px[2*k], t1, fmaf(py[2*k], t2, F))), acc0);

                t1 = fmaf(Qa, px[2*k+1], fmaf(Qb, py[2*k+1], D));
                t2 = fmaf(Qc, py[2*k+1], E);
                acc1 = fmaf(w[2*k+1],
                            ex2f(fmaf(px[2*k+1], t1, fmaf(py[2*k+1], t2, F))), acc1);
            }
            if (s == 0) {
                const float t1 = fmaf(Qa, pxt, fmaf(Qb, pyt, D));
                const float t2 = fmaf(Qc, pyt, E);
                acc0 = fmaf(wt, ex2f(fmaf(pxt, t1, fmaf(pyt, t2, F))), acc0);
            }

            // Reduce over the 8 lanes of this group.
            float acc = acc0 + acc1;
            const unsigned gmask = 0xFFu << (g * 8);
            acc += __shfl_down_sync(gmask, acc, 4, 8);
            acc += __shfl_down_sync(gmask, acc, 2, 8);
            acc += __shfl_down_sync(gmask, acc, 1, 8);

            if (s == 0)
                *oint = fminf(fmaxf(scale * acc, 0.0f), 1.0f);
        }

        P = Pn; qid = qn; p = pn; valid = vnext;
        outb += step_b; oint += pstep;
    }
}

extern "C" void kernel_launch(void* const* d_in, const int* in_sizes, int n_in,
                              void* d_out, int out_size)
{
    const float* means  = (const float*)d_in[0];
    const float* covars = (const float*)d_in[1];
    const float* rots   = (const float*)d_in[2];
    const float* trans  = (const float*)d_in[3];
    const float* eta    = (const float*)d_in[4];
    const float* wts    = (const float*)d_in[5];

    const int npair = in_sizes[0] / 2;

    float* out_pts = (float*)d_out;
    float* out_int = out_pts + (size_t)npair * (size_t)(2 * Q);

    const int blocks = 4096;     // 16384 warps, ~8 quads each at P=524288
    gauss_integral_kernel<<<blocks, TPB>>>(
        means, covars, rots, trans, eta, wts, out_pts, out_int, npair);
}